// round 12
// baseline (speedup 1.0000x reference)
#include <cuda_runtime.h>
#include <cuda_fp16.h>

#define NN 100000
#define NE 2500000
#define NG 1000
#define HD 32
#define NB196 ((NN + 511) / 512)   // 196 chunks of 512

// ---- scratch (__device__ globals; allocation-free) ----
__device__ unsigned g_barcnt;                     // barrier arrivals (self-resetting)
__device__ unsigned g_barsense;                   // barrier sense (even count -> returns to 0)
__device__ __align__(16) float  g_deg[NN];        // dinv
__device__ __align__(16) int    g_cnt[NN];        // histogram (re-zeroed at end of call)
__device__ __align__(16) int    g_scani[NN];
__device__ __align__(16) int    g_bsum[256];
__device__ __align__(16) int    g_off[NN];
__device__ __align__(16) int    g_cur[NN];
__device__ __align__(16) int2   g_csr[NE];        // {src, __float_as_int(ew)}
__device__ __align__(16) float4 g_x[NN];          // dinv[i] * x[i]
__device__ __align__(16) __half g_Ah[NN * HD];
__device__ __align__(16) __half g_Bh[NN * HD];
__device__ __align__(16) float  g_gsum[NG * HD];  // re-zeroed at end of call
__device__ __align__(16) float  g_gcnt[NG];       // re-zeroed at end of call

// software grid barrier (sense reversal). Safe: grid sized for full co-residency.
__device__ __forceinline__ void gbar(int nblocks, unsigned& sense) {
    __syncthreads();
    if (threadIdx.x == 0) {
        sense ^= 1u;
        __threadfence();
        unsigned arrived = atomicAdd(&g_barcnt, 1u);
        if (arrived == (unsigned)nblocks - 1u) {
            g_barcnt = 0u;
            __threadfence();
            atomicExch(&g_barsense, sense);
        } else {
            while (*((volatile unsigned*)&g_barsense) != sense) __nanosleep(64);
        }
        __threadfence();
    }
    __syncthreads();
}

// fp16 gather: warp = 4 edge-groups x 8 lanes, 8 edges/iter, clamped tail.
// Returns (sum_e ew*src[e] + src[i]) replicated across groups.
__device__ __forceinline__ float4 gather_node_h(const uint2* __restrict__ src, int i,
                                                int grp, int sub) {
    int beg = g_off[i];
    int cnt = g_cnt[i];
    float4 acc  = make_float4(0.f, 0.f, 0.f, 0.f);
    float4 acc2 = make_float4(0.f, 0.f, 0.f, 0.f);
    int e = 0;
#pragma unroll 2
    for (; e + 8 <= cnt; e += 8) {
        int2 ce0 = g_csr[beg + e + grp];
        int2 ce1 = g_csr[beg + e + 4 + grp];
        float w0 = __int_as_float(ce0.y);
        float w1 = __int_as_float(ce1.y);
        uint2 u0 = src[(size_t)ce0.x * 8 + sub];
        uint2 u1 = src[(size_t)ce1.x * 8 + sub];
        float2 a01 = __half22float2(*reinterpret_cast<__half2*>(&u0.x));
        float2 a23 = __half22float2(*reinterpret_cast<__half2*>(&u0.y));
        float2 b01 = __half22float2(*reinterpret_cast<__half2*>(&u1.x));
        float2 b23 = __half22float2(*reinterpret_cast<__half2*>(&u1.y));
        acc.x  = fmaf(w0, a01.x, acc.x);  acc.y  = fmaf(w0, a01.y, acc.y);
        acc.z  = fmaf(w0, a23.x, acc.z);  acc.w  = fmaf(w0, a23.y, acc.w);
        acc2.x = fmaf(w1, b01.x, acc2.x); acc2.y = fmaf(w1, b01.y, acc2.y);
        acc2.z = fmaf(w1, b23.x, acc2.z); acc2.w = fmaf(w1, b23.y, acc2.w);
    }
    acc.x += acc2.x; acc.y += acc2.y; acc.z += acc2.z; acc.w += acc2.w;
    if (e + 4 <= cnt) {
        int2 ce = g_csr[beg + e + grp];
        float w = __int_as_float(ce.y);
        uint2 u = src[(size_t)ce.x * 8 + sub];
        float2 a01 = __half22float2(*reinterpret_cast<__half2*>(&u.x));
        float2 a23 = __half22float2(*reinterpret_cast<__half2*>(&u.y));
        acc.x = fmaf(w, a01.x, acc.x); acc.y = fmaf(w, a01.y, acc.y);
        acc.z = fmaf(w, a23.x, acc.z); acc.w = fmaf(w, a23.y, acc.w);
        e += 4;
    }
    int rem = cnt - e;
    if (rem > 0) {
        int g2 = min(grp, rem - 1);              // clamp: valid load, zero weight
        int2 ce = g_csr[beg + e + g2];
        float w = (grp < rem) ? __int_as_float(ce.y) : 0.f;
        uint2 u = src[(size_t)ce.x * 8 + sub];
        float2 a01 = __half22float2(*reinterpret_cast<__half2*>(&u.x));
        float2 a23 = __half22float2(*reinterpret_cast<__half2*>(&u.y));
        acc.x = fmaf(w, a01.x, acc.x); acc.y = fmaf(w, a01.y, acc.y);
        acc.z = fmaf(w, a23.x, acc.z); acc.w = fmaf(w, a23.y, acc.w);
    }
#pragma unroll
    for (int d = 8; d <= 16; d <<= 1) {
        acc.x += __shfl_xor_sync(0xffffffffu, acc.x, d);
        acc.y += __shfl_xor_sync(0xffffffffu, acc.y, d);
        acc.z += __shfl_xor_sync(0xffffffffu, acc.z, d);
        acc.w += __shfl_xor_sync(0xffffffffu, acc.w, d);
    }
    uint2 us = src[(size_t)i * 8 + sub];
    float2 s01 = __half22float2(*reinterpret_cast<__half2*>(&us.x));
    float2 s23 = __half22float2(*reinterpret_cast<__half2*>(&us.y));
    acc.x += s01.x; acc.y += s01.y; acc.z += s23.x; acc.w += s23.y;
    return acc;
}

__global__ void __launch_bounds__(256)
k_mega(const float* __restrict__ x, const void* __restrict__ ei,
       const float* __restrict__ ew, const void* __restrict__ batch,
       const float* __restrict__ W1, const float* __restrict__ b1,
       const float* __restrict__ W2, const float* __restrict__ b2,
       const float* __restrict__ W3, const float* __restrict__ b3,
       const float* __restrict__ lw, const float* __restrict__ lb,
       float* __restrict__ out, int nblocks) {
    __shared__ int   si[256];
    __shared__ float W1s[4 * HD];
    __shared__ float W2s[HD * HD];
    __shared__ float ps[8][HD];
    __shared__ int   sg[8];
    __shared__ int   s_is64;

    int tid = threadIdx.x;
    int bid = blockIdx.x;
    int nthreads = nblocks * 256;
    int gtid = bid * 256 + tid;
    int gwid = gtid >> 5, lane = gtid & 31;
    int nwarps = nthreads >> 5;
    unsigned sense = 0;

    // index-width detect (per block; no cross-block state needed)
    if (tid == 0) {
        const int* p = (const int*)ei;
        int z = 0;
#pragma unroll
        for (int j = 1; j < 64; j += 2) z |= p[j];
        s_is64 = (z == 0) ? 1 : 0;
    }
    __syncthreads();
    bool is64 = (s_is64 != 0);

    // ---- P1: histogram (g_cnt starts zeroed: .bss on first call, cleanup after) ----
    for (int e = gtid; e < NE; e += nthreads) {
        int c = is64 ? (int)((const long long*)ei)[(long long)NE + e]
                     : ((const int*)ei)[(long long)NE + e];
        atomicAdd(&g_cnt[c], 1);
    }
    gbar(nblocks, sense);   // B1

    // ---- P2: per-chunk inclusive scan (512 nodes/chunk, 2 per thread) ----
    for (int c = bid; c < NB196; c += nblocks) {
        int i0 = c * 512 + 2 * tid, i1 = i0 + 1;
        int c0 = (i0 < NN) ? g_cnt[i0] : 0;
        int c1 = (i1 < NN) ? g_cnt[i1] : 0;
        int tsum = c0 + c1;
        si[tid] = tsum;
        __syncthreads();
#pragma unroll
        for (int off = 1; off < 256; off <<= 1) {
            int v = (tid >= off) ? si[tid - off] : 0;
            __syncthreads();
            si[tid] += v;
            __syncthreads();
        }
        int excl = si[tid] - tsum;
        if (i0 < NN) g_scani[i0] = excl + c0;
        if (i1 < NN) g_scani[i1] = excl + c0 + c1;
        if (tid == 255) g_bsum[c] = si[255];
        __syncthreads();
    }
    gbar(nblocks, sense);   // B2

    // ---- P3: scan chunk totals (redundant per block) + node offsets ----
    si[tid] = (tid < NB196) ? g_bsum[tid] : 0;
    __syncthreads();
#pragma unroll
    for (int off = 1; off < 256; off <<= 1) {
        int v = (tid >= off) ? si[tid - off] : 0;
        __syncthreads();
        si[tid] += v;
        __syncthreads();
    }
    for (int i = gtid; i < NN; i += nthreads) {
        int b = i >> 9;
        int add = (b > 0) ? si[b - 1] : 0;
        int excl = add + g_scani[i] - g_cnt[i];
        g_off[i] = excl;
        g_cur[i] = excl;
    }
    gbar(nblocks, sense);   // B3

    // ---- P4: CSR fill ----
    for (int e = gtid; e < NE; e += nthreads) {
        int r = is64 ? (int)((const long long*)ei)[e] : ((const int*)ei)[e];
        int c = is64 ? (int)((const long long*)ei)[(long long)NE + e]
                     : ((const int*)ei)[(long long)NE + e];
        int p = atomicAdd(&g_cur[c], 1);
        g_csr[p] = make_int2(r, __float_as_int(ew[e]));
    }
    gbar(nblocks, sense);   // B4

    // ---- P5: prep (deg from CSR bucket, dinv, prescale x) ----
    for (int i = gwid; i < NN; i += nwarps) {
        int beg = g_off[i];
        int cnt = g_cnt[i];
        float s = 0.f;
        for (int e = lane; e < cnt; e += 32)
            s += __int_as_float(g_csr[beg + e].y);
#pragma unroll
        for (int d = 1; d < 32; d <<= 1)
            s += __shfl_xor_sync(0xffffffffu, s, d);
        float dv = rsqrtf(s + 1.0f);
        if (lane == 0) {
            g_deg[i] = dv;
            float4 xi = __ldg(&reinterpret_cast<const float4*>(x)[i]);
            g_x[i] = make_float4(dv * xi.x, dv * xi.y, dv * xi.z, dv * xi.w);
        }
    }
    gbar(nblocks, sense);   // B5

    // ---- P6: layer 1 ----
    for (int k = tid; k < 4 * HD; k += 256)  W1s[k] = W1[k];
    for (int k = tid; k < HD * HD; k += 256) W2s[k] = W2[k];
    __syncthreads();
    for (int i = gwid; i < NN; i += nwarps) {
        int beg = g_off[i];
        int cnt = g_cnt[i];
        float4 acc = make_float4(0.f, 0.f, 0.f, 0.f);
        for (int e = lane; e < cnt; e += 32) {
            int2 ce = g_csr[beg + e];
            float w = __int_as_float(ce.y);
            float4 xv = g_x[ce.x];
            acc.x = fmaf(w, xv.x, acc.x);
            acc.y = fmaf(w, xv.y, acc.y);
            acc.z = fmaf(w, xv.z, acc.z);
            acc.w = fmaf(w, xv.w, acc.w);
        }
#pragma unroll
        for (int d = 1; d < 32; d <<= 1) {
            acc.x += __shfl_xor_sync(0xffffffffu, acc.x, d);
            acc.y += __shfl_xor_sync(0xffffffffu, acc.y, d);
            acc.z += __shfl_xor_sync(0xffffffffu, acc.z, d);
            acc.w += __shfl_xor_sync(0xffffffffu, acc.w, d);
        }
        float4 xi = g_x[i];
        float dv = g_deg[i];
        acc.x = (acc.x + xi.x) * dv;
        acc.y = (acc.y + xi.y) * dv;
        acc.z = (acc.z + xi.z) * dv;
        acc.w = (acc.w + xi.w) * dv;

        float h = __ldg(&b1[lane]);
        h = fmaf(acc.x, W1s[0 * HD + lane], h);
        h = fmaf(acc.y, W1s[1 * HD + lane], h);
        h = fmaf(acc.z, W1s[2 * HD + lane], h);
        h = fmaf(acc.w, W1s[3 * HD + lane], h);
        h = fmaxf(h, 0.f);

        float o = 0.f;
#pragma unroll
        for (int k = 0; k < HD; k++) {
            float hk = __shfl_sync(0xffffffffu, h, k);
            o = fmaf(hk, W2s[k * HD + lane], o);
        }
        g_Bh[(size_t)i * HD + lane] = __float2half_rn(dv * o);
    }
    gbar(nblocks, sense);   // B6

    // ---- P7: layer 2 ----
    for (int k = tid; k < HD * HD; k += 256) W2s[k] = W3[k];   // reuse smem for W3
    __syncthreads();
    {
        const float4* Ws4 = reinterpret_cast<const float4*>(W2s);
        int grp = lane >> 3, sub = lane & 7;
        for (int i = gwid; i < NN; i += nwarps) {
            float4 v = gather_node_h(reinterpret_cast<const uint2*>(g_Bh), i, grp, sub);
            float dv = g_deg[i];
            float4 b4 = __ldg(&reinterpret_cast<const float4*>(b2)[sub]);
            v.x = fmaxf(fmaf(v.x, dv, b4.x), 0.f);
            v.y = fmaxf(fmaf(v.y, dv, b4.y), 0.f);
            v.z = fmaxf(fmaf(v.z, dv, b4.z), 0.f);
            v.w = fmaxf(fmaf(v.w, dv, b4.w), 0.f);

            float4 o = make_float4(0.f, 0.f, 0.f, 0.f);
#pragma unroll
            for (int j = 0; j < 8; j++) {
                int srcLane = grp * 10 + (j >> 2);
                float comp = ((j & 3) == 0) ? v.x : ((j & 3) == 1) ? v.y
                           : ((j & 3) == 2) ? v.z : v.w;
                float vk = __shfl_sync(0xffffffffu, comp, srcLane);
                float4 w4 = Ws4[(grp * 8 + j) * 8 + sub];
                o.x = fmaf(vk, w4.x, o.x); o.y = fmaf(vk, w4.y, o.y);
                o.z = fmaf(vk, w4.z, o.z); o.w = fmaf(vk, w4.w, o.w);
            }
#pragma unroll
            for (int d = 8; d <= 16; d <<= 1) {
                o.x += __shfl_xor_sync(0xffffffffu, o.x, d);
                o.y += __shfl_xor_sync(0xffffffffu, o.y, d);
                o.z += __shfl_xor_sync(0xffffffffu, o.z, d);
                o.w += __shfl_xor_sync(0xffffffffu, o.w, d);
            }
            if (grp == 0) {
                __half2 p0 = __floats2half2_rn(dv * o.x, dv * o.y);
                __half2 p1 = __floats2half2_rn(dv * o.z, dv * o.w);
                uint2 st;
                st.x = *reinterpret_cast<unsigned*>(&p0);
                st.y = *reinterpret_cast<unsigned*>(&p1);
                reinterpret_cast<uint2*>(g_Ah)[(size_t)i * 8 + sub] = st;
            }
        }
    }
    gbar(nblocks, sense);   // B7

    // ---- P8: layer 3 gather + sorted-batch mean-pool ----
    {
        int warpid = tid >> 5;
        int llane = tid & 31, grp = llane >> 3, sub = llane & 7;
        int ngroups = NN / 8;   // 12500, block handles 8 consecutive nodes/iter
        for (int gset = bid; gset < ngroups; gset += nblocks) {
            int i = gset * 8 + warpid;
            float4 v = gather_node_h(reinterpret_cast<const uint2*>(g_Ah), i, grp, sub);
            float dv = g_deg[i];
            float4 b4 = __ldg(&reinterpret_cast<const float4*>(b3)[sub]);
            v.x = fmaf(v.x, dv, b4.x);
            v.y = fmaf(v.y, dv, b4.y);
            v.z = fmaf(v.z, dv, b4.z);
            v.w = fmaf(v.w, dv, b4.w);
            if (grp == 0)
                *reinterpret_cast<float4*>(&ps[warpid][sub * 4]) = v;
            if (llane == 0)
                sg[warpid] = is64 ? (int)((const long long*)batch)[i]
                                  : ((const int*)batch)[i];
            __syncthreads();
            if (tid < HD) {
                int g0 = sg[0];
                if (g0 == sg[7]) {
                    float sum = 0.f;
#pragma unroll
                    for (int w = 0; w < 8; w++) sum += ps[w][tid];
                    atomicAdd(&g_gsum[g0 * HD + tid], sum);
                    if (tid == 0) atomicAdd(&g_gcnt[g0], 8.0f);
                } else {
#pragma unroll
                    for (int w = 0; w < 8; w++)
                        atomicAdd(&g_gsum[sg[w] * HD + tid], ps[w][tid]);
                    if (tid == 0) {
#pragma unroll
                        for (int w = 0; w < 8; w++) atomicAdd(&g_gcnt[sg[w]], 1.0f);
                    }
                }
            }
            __syncthreads();
        }
    }
    gbar(nblocks, sense);   // B8

    // ---- P9: head ----
    for (int g = gtid; g < NG; g += nthreads) {
        float inv = 1.0f / fmaxf(g_gcnt[g], 1.0f);
        float l0 = __ldg(&lb[0]), l1 = __ldg(&lb[1]), l2 = __ldg(&lb[2]);
#pragma unroll 8
        for (int k = 0; k < HD; k++) {
            float p = g_gsum[g * HD + k] * inv;
            l0 += p * __ldg(&lw[k * 3 + 0]);
            l1 += p * __ldg(&lw[k * 3 + 1]);
            l2 += p * __ldg(&lw[k * 3 + 2]);
        }
        float m = fmaxf(l0, fmaxf(l1, l2));
        float e0 = expf(l0 - m), e1 = expf(l1 - m), e2 = expf(l2 - m);
        float s = 1.0f / (e0 + e1 + e2);
        out[g * 3 + 0] = e0 * s;
        out[g * 3 + 1] = e1 * s;
        out[g * 3 + 2] = e2 * s;
    }
    gbar(nblocks, sense);   // B9

    // ---- P10: reset scratch for the next (replayed) call ----
    for (int i = gtid; i < NN; i += nthreads) g_cnt[i] = 0;
    for (int i = gtid; i < NG * HD; i += nthreads) g_gsum[i] = 0.f;
    for (int i = gtid; i < NG; i += nthreads) g_gcnt[i] = 0.f;
    gbar(nblocks, sense);   // B10 (even count: sense returns to 0 for next call)
}

extern "C" void kernel_launch(void* const* d_in, const int* in_sizes, int n_in,
                              void* d_out, int out_size) {
    const float* x     = (const float*)d_in[0];
    const void*  ei    = d_in[1];
    const float* ew    = (const float*)d_in[2];
    const void*  batch = d_in[3];
    const float* W1    = (const float*)d_in[4];
    const float* b1    = (const float*)d_in[5];
    const float* W2    = (const float*)d_in[6];
    const float* b2    = (const float*)d_in[7];
    const float* W3    = (const float*)d_in[8];
    const float* b3    = (const float*)d_in[9];
    const float* lw    = (const float*)d_in[10];
    const float* lb    = (const float*)d_in[11];
    float* out = (float*)d_out;

    // exact co-residency: grid = blocksPerSM * numSMs (deadlock-free barrier)
    static int grid = 0;
    if (grid == 0) {
        int dev = 0, nsm = 0, bpm = 0;
        cudaGetDevice(&dev);
        cudaDeviceGetAttribute(&nsm, cudaDevAttrMultiProcessorCount, dev);
        cudaOccupancyMaxActiveBlocksPerMultiprocessor(&bpm, k_mega, 256, 0);
        if (bpm < 1) bpm = 1;
        grid = nsm * bpm;
    }
    k_mega<<<grid, 256>>>(x, ei, ew, batch, W1, b1, W2, b2, W3, b3, lw, lb, out, grid);
}

// round 13
// speedup vs baseline: 1.1754x; 1.1754x over previous
#include <cuda_runtime.h>
#include <cuda_fp16.h>

#define NN 100000
#define NE 2500000
#define NG 1000
#define HD 32
#define SCAN_B 512
#define NB ((NN + SCAN_B - 1) / SCAN_B)   // 196

// ---- scratch (__device__ globals; allocation-free) ----
__device__ int   g_is64;
__device__ __align__(16) float  g_deg[NN];        // dinv (written by k_prep)
__device__ __align__(16) int    g_cnt[NN];
__device__ __align__(16) int    g_scani[NN];
__device__ __align__(16) int    g_bsum[256];
__device__ __align__(16) int    g_off[NN];
__device__ __align__(16) int    g_cur[NN];
__device__ __align__(16) int2   g_csr[NE];        // {src, packed half2{w,w}}
__device__ __align__(16) float4 g_x[NN];          // dinv[i] * x[i]
__device__ __align__(16) __half g_Ah[NN * HD];    // fp16 prescaled features
__device__ __align__(16) __half g_Bh[NN * HD];
__device__ __align__(16) float  g_gsum[NG * HD];
__device__ __align__(16) float  g_gcnt[NG];

__device__ __forceinline__ int ldidx(const void* p, long long e) {
    if (g_is64) return (int)((const long long*)p)[e];
    return ((const int*)p)[e];
}

__global__ void k_init(const void* ei) {
    int t = blockIdx.x * blockDim.x + threadIdx.x;
    if (t == 0) {
        const int* p = (const int*)ei;
        int z = 0;
#pragma unroll
        for (int j = 1; j < 64; j += 2) z |= p[j];
        g_is64 = (z == 0) ? 1 : 0;
    }
    if (t < NN) g_cnt[t] = 0;
    if (t < NG * HD) g_gsum[t] = 0.f;
    if (t < NG) g_gcnt[t] = 0.f;
}

__global__ void k_hist(const void* __restrict__ ei) {
    int e = blockIdx.x * blockDim.x + threadIdx.x;
    if (e >= NE) return;
    int c = ldidx(ei, (long long)NE + e);
    atomicAdd(&g_cnt[c], 1);
}

__global__ void k_scan1() {
    __shared__ int s[SCAN_B];
    int tid = threadIdx.x;
    int i = blockIdx.x * SCAN_B + tid;
    s[tid] = (i < NN) ? g_cnt[i] : 0;
    __syncthreads();
#pragma unroll
    for (int off = 1; off < SCAN_B; off <<= 1) {
        int v = (tid >= off) ? s[tid - off] : 0;
        __syncthreads();
        s[tid] += v;
        __syncthreads();
    }
    if (i < NN) g_scani[i] = s[tid];
    if (tid == SCAN_B - 1) g_bsum[blockIdx.x] = s[tid];
}

// merged scan2+scan3
__global__ void k_scan23() {
    __shared__ int s[256];
    int tid = threadIdx.x;
    s[tid] = (tid < NB) ? g_bsum[tid] : 0;
    __syncthreads();
#pragma unroll
    for (int off = 1; off < 256; off <<= 1) {
        int v = (tid >= off) ? s[tid - off] : 0;
        __syncthreads();
        s[tid] += v;
        __syncthreads();
    }
    int i = blockIdx.x * blockDim.x + tid;
    if (i >= NN) return;
    int b = i / SCAN_B;
    int add = (b > 0) ? s[b - 1] : 0;
    int excl = add + g_scani[i] - g_cnt[i];
    g_off[i] = excl;
    g_cur[i] = excl;
}

// CSR fill: weight packed once as half2{w,w} -> zero per-edge conversion later
__global__ void k_fill(const void* __restrict__ ei, const float* __restrict__ ew) {
    int e = blockIdx.x * blockDim.x + threadIdx.x;
    if (e >= NE) return;
    int r = ldidx(ei, e);
    int c = ldidx(ei, (long long)NE + e);
    int p = atomicAdd(&g_cur[c], 1);
    float w = ew[e];
    __half2 wp = __floats2half2_rn(w, w);
    g_csr[p] = make_int2(r, *reinterpret_cast<int*>(&wp));
}

// warp per node: deg = coalesced bucket sum (weights from half), dinv, prescale x.
__global__ void k_prep(const float* __restrict__ x) {
    int t = blockIdx.x * blockDim.x + threadIdx.x;
    int i = t >> 5, lane = t & 31;
    if (i >= NN) return;
    int beg = g_off[i];
    int cnt = g_cnt[i];
    float s = 0.f;
    for (int e = lane; e < cnt; e += 32) {
        int wb = g_csr[beg + e].y;
        s += __low2float(*reinterpret_cast<__half2*>(&wb));
    }
#pragma unroll
    for (int d = 1; d < 32; d <<= 1)
        s += __shfl_xor_sync(0xffffffffu, s, d);
    float dv = rsqrtf(s + 1.0f);
    if (lane == 0) {
        g_deg[i] = dv;
        float4 xi = __ldg(&reinterpret_cast<const float4*>(x)[i]);
        g_x[i] = make_float4(dv * xi.x, dv * xi.y, dv * xi.z, dv * xi.w);
    }
}

// Layer 1: gather prescaled 16B fp32 x rows (lane-strided);
// h1 = relu(dv*(sum+self)@W1+b1); store g_Bh[i] = fp16(dv * (h1@W2)).
__global__ void k_layer1(const float* __restrict__ W1, const float* __restrict__ b1,
                         const float* __restrict__ W2) {
    __shared__ float W1s[4 * HD];
    __shared__ float W2s[HD * HD];
    int tid = threadIdx.x;
    for (int k = tid; k < 4 * HD; k += blockDim.x)  W1s[k] = W1[k];
    for (int k = tid; k < HD * HD; k += blockDim.x) W2s[k] = W2[k];
    __syncthreads();
    int t = blockIdx.x * blockDim.x + tid;
    int i = t >> 5, lane = t & 31;
    if (i >= NN) return;

    int beg = g_off[i];
    int cnt = g_cnt[i];
    float4 acc = make_float4(0.f, 0.f, 0.f, 0.f);
    for (int e = lane; e < cnt; e += 32) {
        int2 ce = g_csr[beg + e];
        float w = __low2float(*reinterpret_cast<__half2*>(&ce.y));
        float4 xv = g_x[ce.x];
        acc.x = fmaf(w, xv.x, acc.x);
        acc.y = fmaf(w, xv.y, acc.y);
        acc.z = fmaf(w, xv.z, acc.z);
        acc.w = fmaf(w, xv.w, acc.w);
    }
#pragma unroll
    for (int d = 1; d < 32; d <<= 1) {
        acc.x += __shfl_xor_sync(0xffffffffu, acc.x, d);
        acc.y += __shfl_xor_sync(0xffffffffu, acc.y, d);
        acc.z += __shfl_xor_sync(0xffffffffu, acc.z, d);
        acc.w += __shfl_xor_sync(0xffffffffu, acc.w, d);
    }
    float4 xi = g_x[i];
    float dv = g_deg[i];
    acc.x = (acc.x + xi.x) * dv;
    acc.y = (acc.y + xi.y) * dv;
    acc.z = (acc.z + xi.z) * dv;
    acc.w = (acc.w + xi.w) * dv;

    float h = __ldg(&b1[lane]);
    h = fmaf(acc.x, W1s[0 * HD + lane], h);
    h = fmaf(acc.y, W1s[1 * HD + lane], h);
    h = fmaf(acc.z, W1s[2 * HD + lane], h);
    h = fmaf(acc.w, W1s[3 * HD + lane], h);
    h = fmaxf(h, 0.f);

    float o = 0.f;
#pragma unroll
    for (int k = 0; k < HD; k++) {
        float hk = __shfl_sync(0xffffffffu, h, k);
        o = fmaf(hk, W2s[k * HD + lane], o);
    }
    g_Bh[(size_t)i * HD + lane] = __float2half_rn(dv * o);
}

// HFMA2 fp16 gather: warp = 4 edge-groups x 8 lanes, 8 edges/iter.
// Accumulates in __half2 (2 HFMA2/edge/lane), converts to fp32 at reduction.
// Returns (sum_e w*src[e] + src[i]) replicated across groups.
__device__ __forceinline__ float4 gather_node_h2(const uint2* __restrict__ src, int i,
                                                 int grp, int sub) {
    int beg = g_off[i];
    int cnt = g_cnt[i];
    const __half2 hz = __floats2half2_rn(0.f, 0.f);
    __half2 a01 = hz, a23 = hz, b01 = hz, b23 = hz;
    int e = 0;
#pragma unroll 2
    for (; e + 8 <= cnt; e += 8) {
        int2 ce0 = g_csr[beg + e + grp];
        int2 ce1 = g_csr[beg + e + 4 + grp];
        __half2 w0 = *reinterpret_cast<__half2*>(&ce0.y);
        __half2 w1 = *reinterpret_cast<__half2*>(&ce1.y);
        uint2 u0 = src[(size_t)ce0.x * 8 + sub];
        uint2 u1 = src[(size_t)ce1.x * 8 + sub];
        a01 = __hfma2(w0, *reinterpret_cast<__half2*>(&u0.x), a01);
        a23 = __hfma2(w0, *reinterpret_cast<__half2*>(&u0.y), a23);
        b01 = __hfma2(w1, *reinterpret_cast<__half2*>(&u1.x), b01);
        b23 = __hfma2(w1, *reinterpret_cast<__half2*>(&u1.y), b23);
    }
    if (e + 4 <= cnt) {
        int2 ce = g_csr[beg + e + grp];
        __half2 w = *reinterpret_cast<__half2*>(&ce.y);
        uint2 u = src[(size_t)ce.x * 8 + sub];
        a01 = __hfma2(w, *reinterpret_cast<__half2*>(&u.x), a01);
        a23 = __hfma2(w, *reinterpret_cast<__half2*>(&u.y), a23);
        e += 4;
    }
    int rem = cnt - e;                           // 0..3
    if (rem > 0) {
        int g2 = min(grp, rem - 1);              // clamp: valid load, zero weight
        int2 ce = g_csr[beg + e + g2];
        int wb = (grp < rem) ? ce.y : 0;
        __half2 w = *reinterpret_cast<__half2*>(&wb);
        uint2 u = src[(size_t)ce.x * 8 + sub];
        a01 = __hfma2(w, *reinterpret_cast<__half2*>(&u.x), a01);
        a23 = __hfma2(w, *reinterpret_cast<__half2*>(&u.y), a23);
    }
    // convert chains to fp32 and combine
    float2 fa01 = __half22float2(a01), fa23 = __half22float2(a23);
    float2 fb01 = __half22float2(b01), fb23 = __half22float2(b23);
    float4 acc = make_float4(fa01.x + fb01.x, fa01.y + fb01.y,
                             fa23.x + fb23.x, fa23.y + fb23.y);
#pragma unroll
    for (int d = 8; d <= 16; d <<= 1) {          // reduce across the 4 groups
        acc.x += __shfl_xor_sync(0xffffffffu, acc.x, d);
        acc.y += __shfl_xor_sync(0xffffffffu, acc.y, d);
        acc.z += __shfl_xor_sync(0xffffffffu, acc.z, d);
        acc.w += __shfl_xor_sync(0xffffffffu, acc.w, d);
    }
    uint2 us = src[(size_t)i * 8 + sub];         // self row (prescaled)
    float2 s01 = __half22float2(*reinterpret_cast<__half2*>(&us.x));
    float2 s23 = __half22float2(*reinterpret_cast<__half2*>(&us.y));
    acc.x += s01.x; acc.y += s01.y; acc.z += s23.x; acc.w += s23.y;
    return acc;
}

// Layer 2: gather g_Bh; v = relu(dv*acc + b2); o = v@W3; g_Ah = fp16(dv*o).
__global__ void k_layer2(const float* __restrict__ bias, const float* __restrict__ W) {
    __shared__ float4 Ws[HD * 8];                 // W[k][f] as float4: Ws[k*8 + sub]
    int tid = threadIdx.x;
    for (int k = tid; k < HD * 8; k += blockDim.x)
        Ws[k] = reinterpret_cast<const float4*>(W)[k];
    __syncthreads();
    int t = blockIdx.x * blockDim.x + tid;
    int i = t >> 5, lane = t & 31, grp = lane >> 3, sub = lane & 7;
    if (i >= NN) return;

    float4 v = gather_node_h2(reinterpret_cast<const uint2*>(g_Bh), i, grp, sub);
    float dv = g_deg[i];
    float4 b4 = __ldg(&reinterpret_cast<const float4*>(bias)[sub]);
    v.x = fmaxf(fmaf(v.x, dv, b4.x), 0.f);
    v.y = fmaxf(fmaf(v.y, dv, b4.y), 0.f);
    v.z = fmaxf(fmaf(v.z, dv, b4.z), 0.f);
    v.w = fmaxf(fmaf(v.w, dv, b4.w), 0.f);

    float4 o = make_float4(0.f, 0.f, 0.f, 0.f);
#pragma unroll
    for (int j = 0; j < 8; j++) {
        int srcLane = grp * 10 + (j >> 2);        // = grp*8 + ((grp*8+j)>>2)
        float comp = ((j & 3) == 0) ? v.x : ((j & 3) == 1) ? v.y
                   : ((j & 3) == 2) ? v.z : v.w;
        float vk = __shfl_sync(0xffffffffu, comp, srcLane);
        float4 w4 = Ws[(grp * 8 + j) * 8 + sub];
        o.x = fmaf(vk, w4.x, o.x); o.y = fmaf(vk, w4.y, o.y);
        o.z = fmaf(vk, w4.z, o.z); o.w = fmaf(vk, w4.w, o.w);
    }
#pragma unroll
    for (int d = 8; d <= 16; d <<= 1) {
        o.x += __shfl_xor_sync(0xffffffffu, o.x, d);
        o.y += __shfl_xor_sync(0xffffffffu, o.y, d);
        o.z += __shfl_xor_sync(0xffffffffu, o.z, d);
        o.w += __shfl_xor_sync(0xffffffffu, o.w, d);
    }
    if (grp == 0) {
        __half2 p0 = __floats2half2_rn(dv * o.x, dv * o.y);
        __half2 p1 = __floats2half2_rn(dv * o.z, dv * o.w);
        uint2 st;
        st.x = *reinterpret_cast<unsigned*>(&p0);
        st.y = *reinterpret_cast<unsigned*>(&p1);
        reinterpret_cast<uint2*>(g_Ah)[(size_t)i * 8 + sub] = st;
    }
}

// Layer 3: gather g_Ah; v = dv*acc + b3; sorted-batch mean-pool.
__global__ void k_gather_pool(const float* __restrict__ bias,
                              const void* __restrict__ batch) {
    __shared__ float s[8][HD];
    __shared__ int sg[8];
    int tid = threadIdx.x;
    int t = blockIdx.x * blockDim.x + tid;
    int i = t >> 5, lane = t & 31, grp = lane >> 3, sub = lane & 7;
    int warpid = tid >> 5;
    float4 v = gather_node_h2(reinterpret_cast<const uint2*>(g_Ah), i, grp, sub);
    float dv = g_deg[i];
    float4 b4 = __ldg(&reinterpret_cast<const float4*>(bias)[sub]);
    v.x = fmaf(v.x, dv, b4.x);
    v.y = fmaf(v.y, dv, b4.y);
    v.z = fmaf(v.z, dv, b4.z);
    v.w = fmaf(v.w, dv, b4.w);
    if (grp == 0)
        *reinterpret_cast<float4*>(&s[warpid][sub * 4]) = v;
    if (lane == 0) sg[warpid] = ldidx(batch, i);
    __syncthreads();
    if (tid < HD) {
        int g0 = sg[0];
        if (g0 == sg[7]) {                        // sorted => all 8 equal
            float sum = 0.f;
#pragma unroll
            for (int w = 0; w < 8; w++) sum += s[w][tid];
            atomicAdd(&g_gsum[g0 * HD + tid], sum);
            if (tid == 0) atomicAdd(&g_gcnt[g0], 8.0f);
        } else {
#pragma unroll
            for (int w = 0; w < 8; w++)
                atomicAdd(&g_gsum[sg[w] * HD + tid], s[w][tid]);
            if (tid == 0) {
#pragma unroll
                for (int w = 0; w < 8; w++) atomicAdd(&g_gcnt[sg[w]], 1.0f);
            }
        }
    }
}

__global__ void k_head(const float* __restrict__ lw, const float* __restrict__ lb,
                       float* __restrict__ out) {
    int g = blockIdx.x * blockDim.x + threadIdx.x;
    if (g >= NG) return;
    float inv = 1.0f / fmaxf(g_gcnt[g], 1.0f);
    float l0 = __ldg(&lb[0]), l1 = __ldg(&lb[1]), l2 = __ldg(&lb[2]);
#pragma unroll 8
    for (int k = 0; k < HD; k++) {
        float p = g_gsum[g * HD + k] * inv;
        l0 += p * __ldg(&lw[k * 3 + 0]);
        l1 += p * __ldg(&lw[k * 3 + 1]);
        l2 += p * __ldg(&lw[k * 3 + 2]);
    }
    float m = fmaxf(l0, fmaxf(l1, l2));
    float e0 = expf(l0 - m), e1 = expf(l1 - m), e2 = expf(l2 - m);
    float s = 1.0f / (e0 + e1 + e2);
    out[g * 3 + 0] = e0 * s;
    out[g * 3 + 1] = e1 * s;
    out[g * 3 + 2] = e2 * s;
}

extern "C" void kernel_launch(void* const* d_in, const int* in_sizes, int n_in,
                              void* d_out, int out_size) {
    const float* x     = (const float*)d_in[0];
    const void*  ei    = d_in[1];
    const float* ew    = (const float*)d_in[2];
    const void*  batch = d_in[3];
    const float* W1    = (const float*)d_in[4];
    const float* b1    = (const float*)d_in[5];
    const float* W2    = (const float*)d_in[6];
    const float* b2    = (const float*)d_in[7];
    const float* W3    = (const float*)d_in[8];
    const float* b3    = (const float*)d_in[9];
    const float* lw    = (const float*)d_in[10];
    const float* lb    = (const float*)d_in[11];
    float* out = (float*)d_out;

    const int B = 256;
    const int gbN  = (NN + B - 1) / B;
    const int gbE  = (NE + B - 1) / B;
    const int gbNH = (NN * HD) / B;           // 12500 blocks, 8 nodes each

    k_init<<<gbN, B>>>(ei);
    k_hist<<<gbE, B>>>(ei);
    k_scan1<<<NB, SCAN_B>>>();
    k_scan23<<<gbN, B>>>();
    k_fill<<<gbE, B>>>(ei, ew);
    k_prep<<<gbNH, B>>>(x);

    k_layer1<<<gbNH, B>>>(W1, b1, W2);        // gather g_x -> g_Bh (fp16)
    k_layer2<<<gbNH, B>>>(b2, W3);            // HFMA2 gather g_Bh -> g_Ah (fp16)
    k_gather_pool<<<gbNH, B>>>(b3, batch);    // HFMA2 gather g_Ah + pool
    k_head<<<(NG + B - 1) / B, B>>>(lw, lb, out);
}